// round 15
// baseline (speedup 1.0000x reference)
#include <cuda_runtime.h>

// Problem constants (shapes fixed by the dataset).
#define NE_MAX 100000
#define NR_MAX 1000
#define NB_MAX 131072

// Scratch (allocation-free: __device__ globals, zero-initialized at load).
__device__ float2 g_ve[NE_MAX * 16];   // 12.8 MB per-entity state vectors
__device__ float2 g_mr[NR_MAX * 256];  // 2.0 MB per-relation 16x16 matrices
__device__ int g_hist[NR_MAX];         // relation counts   (INVARIANT: zero at entry)
__device__ int g_bump[NR_MAX];         // per-bin bump ctrs (INVARIANT: zero at entry)
__device__ int4 g_pack[NB_MAX];        // relation-grouped {b, h[b], r[b], t[b]}

// ---------------------------------------------------------------------------
// Gate math. Angles in [-pi/10, pi/10] -> __sincosf is inside the 1e-3 budget.
// ---------------------------------------------------------------------------
__device__ __forceinline__ void rot_mat(float phi, float th, float om,
                                        float2& m00, float2& m01,
                                        float2& m10, float2& m11) {
    float st, ct, sa, ca, sb, cb;
    __sincosf(0.5f * th, &st, &ct);
    __sincosf(0.5f * (phi + om), &sa, &ca);
    __sincosf(0.5f * (phi - om), &sb, &cb);
    m00 = make_float2(ca * ct, -sa * ct);
    m01 = make_float2(-cb * st, -sb * st);
    m10 = make_float2(cb * st, -sb * st);
    m11 = make_float2(ca * ct, sa * ct);
}

__device__ __forceinline__ float2 cmul(float2 x, float2 y) {
    return make_float2(x.x * y.x - x.y * y.y, x.x * y.y + x.y * y.x);
}

__device__ __forceinline__ float2 cadd(float2 x, float2 y) {
    return make_float2(x.x + y.x, x.y + y.y);
}

__device__ __forceinline__ void gate_pair(float2& a, float2& b,
                                          float2 m00, float2 m01,
                                          float2 m10, float2 m11) {
    float2 na, nb;
    na.x = m00.x * a.x - m00.y * a.y + m01.x * b.x - m01.y * b.y;
    na.y = m00.x * a.y + m00.y * a.x + m01.x * b.y + m01.y * b.x;
    nb.x = m10.x * a.x - m10.y * a.y + m11.x * b.x - m11.y * b.y;
    nb.y = m10.x * a.y + m10.y * a.x + m11.x * b.y + m11.y * b.x;
    a = na; b = nb;
}

// CRot layers (off = 1..3) on a full 16-amplitude register state.
__device__ __forceinline__ void apply_crot_layers(float2 s[16], const float p[48]) {
    #pragma unroll
    for (int off = 1; off <= 3; off++) {
        #pragma unroll
        for (int q = 0; q < 4; q++) {
            const int t = (q + off) & 3;
            const int base = (off * 4 + q) * 3;
            float2 m00, m01, m10, m11;
            rot_mat(p[base + 0], p[base + 1], p[base + 2], m00, m01, m10, m11);
            const int sc = 8 >> q;
            const int st = 8 >> t;
            #pragma unroll
            for (int i = 0; i < 16; i++) {
                if (!(i & sc) || (i & st)) continue;  // control=1, target bit=0
                gate_pair(s[i], s[i + st], m00, m01, m10, m11);
            }
        }
    }
}

__device__ __forceinline__ void load_params48(const float* __restrict__ g, float p[48]) {
    const float4* g4 = reinterpret_cast<const float4*>(g);
    #pragma unroll
    for (int i = 0; i < 12; i++) {
        float4 v = __ldg(g4 + i);
        p[i * 4 + 0] = v.x; p[i * 4 + 1] = v.y;
        p[i * 4 + 2] = v.z; p[i * 4 + 3] = v.w;
    }
}

// Build s[16] = product state from per-qubit 2-vectors w0..w3.
__device__ __forceinline__ void build_product(float2 s[16],
                                              const float2 w0[2], const float2 w1[2],
                                              const float2 w2[2], const float2 w3[2]) {
    float2 a01[4], a23[4];
    #pragma unroll
    for (int k = 0; k < 4; k++) {
        a01[k] = cmul(w0[k >> 1], w1[k & 1]);
        a23[k] = cmul(w2[k >> 1], w3[k & 1]);
    }
    #pragma unroll
    for (int i = 0; i < 16; i++)
        s[i] = cmul(a01[i >> 2], a23[i & 3]);
}

// ---------------------------------------------------------------------------
// Fused prep kernel: entities | relations | histogram, split by blockIdx.
// Layer 0 uses the product-state shortcut in both circuit jobs.
// ---------------------------------------------------------------------------
#define HIST_BLOCKS 64

__global__ void prep_kernel(const float* __restrict__ ep, int E, int EB,
                            const float* __restrict__ rp, int R, int RB,
                            const int* __restrict__ r, int B) {
    __shared__ int sh[NR_MAX];

    if (blockIdx.x < EB) {
        // ---- entity job: v_e = U(ep[e]) * |+>^4 ----
        int e = blockIdx.x * blockDim.x + threadIdx.x;
        if (e >= E) return;
        float p[48];
        load_params48(ep + (size_t)e * 48, p);

        float2 w[4][2];
        #pragma unroll
        for (int q = 0; q < 4; q++) {
            float2 m00, m01, m10, m11;
            rot_mat(p[q * 3 + 0], p[q * 3 + 1], p[q * 3 + 2], m00, m01, m10, m11);
            w[q][0] = cadd(m00, m01);
            w[q][1] = cadd(m10, m11);
        }
        w[0][0].x *= 0.25f; w[0][0].y *= 0.25f;
        w[0][1].x *= 0.25f; w[0][1].y *= 0.25f;

        float2 s[16];
        build_product(s, w[0], w[1], w[2], w[3]);
        apply_crot_layers(s, p);

        float4* dst = reinterpret_cast<float4*>(g_ve + e * 16);
        #pragma unroll
        for (int i = 0; i < 8; i++)
            dst[i] = make_float4(s[2 * i].x, s[2 * i].y, s[2 * i + 1].x, s[2 * i + 1].y);
    } else if (blockIdx.x < EB + RB) {
        // ---- relation job: M_r column col = U(rp[r]) * e_col ----
        int idx = (blockIdx.x - EB) * blockDim.x + threadIdx.x;
        int rr = idx >> 4;
        int col = idx & 15;
        if (rr >= R) return;
        float p[48];
        load_params48(rp + (size_t)rr * 48, p);

        float2 w[4][2];
        #pragma unroll
        for (int q = 0; q < 4; q++) {
            float2 m00, m01, m10, m11;
            rot_mat(p[q * 3 + 0], p[q * 3 + 1], p[q * 3 + 2], m00, m01, m10, m11);
            int cb = (col >> (3 - q)) & 1;     // qubit q's bit of |col>
            w[q][0] = cb ? m01 : m00;
            w[q][1] = cb ? m11 : m10;
        }

        float2 s[16];
        build_product(s, w[0], w[1], w[2], w[3]);
        apply_crot_layers(s, p);

        #pragma unroll
        for (int i = 0; i < 16; i++)
            g_mr[rr * 256 + i * 16 + col] = s[i];
    } else {
        // ---- histogram job (smem-privatized; g_hist zero at entry) ----
        int hb = blockIdx.x - EB - RB;
        for (int i = threadIdx.x; i < NR_MAX; i += blockDim.x) sh[i] = 0;
        __syncthreads();
        int chunk = (B + HIST_BLOCKS - 1) / HIST_BLOCKS;
        int start = hb * chunk;
        int end = min(start + chunk, B);
        for (int b = start + threadIdx.x; b < end; b += blockDim.x)
            atomicAdd(&sh[r[b]], 1);
        __syncthreads();
        for (int i = threadIdx.x; i < NR_MAX; i += blockDim.x) {
            int c = sh[i];
            if (c) atomicAdd(&g_hist[i], c);
        }
    }
}

// ---------------------------------------------------------------------------
// Scatter with integrated scan. 128 blocks (finer chunks, better SM fill).
// ---------------------------------------------------------------------------
#define SCAT_BLOCKS 128

__global__ void __launch_bounds__(256) scatter_kernel(
        const int* __restrict__ h, const int* __restrict__ r,
        const int* __restrict__ t, int B) {
    __shared__ int cnt[NR_MAX];
    __shared__ int gbase[NR_MAX];
    __shared__ int wbase[NR_MAX];
    __shared__ int wsum[8];

    const int tid = threadIdx.x;
    for (int i = tid; i < NR_MAX; i += blockDim.x) cnt[i] = 0;

    int hv[4], pre[4];
    int tsum = 0;
    #pragma unroll
    for (int k = 0; k < 4; k++) {
        int bin = 4 * tid + k;
        hv[k] = (bin < NR_MAX) ? g_hist[bin] : 0;
        pre[k] = tsum;
        tsum += hv[k];
    }
    int x = tsum;
    #pragma unroll
    for (int d = 1; d < 32; d <<= 1) {
        int y = __shfl_up_sync(0xffffffffu, x, d);
        if ((tid & 31) >= d) x += y;
    }
    if ((tid & 31) == 31) wsum[tid >> 5] = x;
    __syncthreads();
    if (tid < 8) {
        int s = wsum[tid];
        #pragma unroll
        for (int d = 1; d < 8; d <<= 1) {
            int y = __shfl_up_sync(0xffu, s, d);
            if (tid >= d) s += y;
        }
        wsum[tid] = s;
    }
    __syncthreads();
    int excl = x - tsum + ((tid >= 32) ? wsum[(tid >> 5) - 1] : 0);
    #pragma unroll
    for (int k = 0; k < 4; k++) {
        int bin = 4 * tid + k;
        if (bin < NR_MAX) gbase[bin] = excl + pre[k];
    }
    __syncthreads();

    int chunk = (B + SCAT_BLOCKS - 1) / SCAT_BLOCKS;
    int start = blockIdx.x * chunk;
    int end = min(start + chunk, B);
    for (int b = start + tid; b < end; b += blockDim.x)
        atomicAdd(&cnt[r[b]], 1);
    __syncthreads();

    for (int i = tid; i < NR_MAX; i += blockDim.x) {
        int c = cnt[i];
        wbase[i] = c ? gbase[i] + atomicAdd(&g_bump[i], c) : 0;
        cnt[i] = 0;
    }
    __syncthreads();

    for (int b = start + tid; b < end; b += blockDim.x) {
        int rr = r[b];
        int pos = wbase[rr] + atomicAdd(&cnt[rr], 1);
        g_pack[pos] = make_int4(b, h[b], rr, t[b]);
    }
}

// ---------------------------------------------------------------------------
// Score: 4 threads per item, 4 rows each. vt read from smem at accumulate
// time (saves 8 regs); launch_bounds(256,6) -> 6 blocks/SM = 75% occupancy
// (was register-quantized to 5 blocks / 62.5%).
// ---------------------------------------------------------------------------
#define SC_ITEMS 64            // items per block
#define SC_THREADS 256         // 4 threads per item

__global__ void __launch_bounds__(SC_THREADS, 6) score_kernel(float* __restrict__ out, int B) {
    __shared__ float4 sv_h[SC_ITEMS * 8];   // 4 KB, (chunk+item)&7 swizzle
    __shared__ float4 sv_t[SC_ITEMS * 8];   // 4 KB
    __shared__ int sh_h[SC_ITEMS];
    __shared__ int sh_t[SC_ITEMS];
    __shared__ int sh_r[SC_ITEMS];
    __shared__ int sh_b[SC_ITEMS];
    __shared__ float sred[SC_THREADS];

    const int tid = threadIdx.x;
    const int start = blockIdx.x * SC_ITEMS;

    // Re-zero sort scratch for the next graph replay (block 0 only).
    if (blockIdx.x == 0) {
        for (int i = tid; i < NR_MAX; i += SC_THREADS) {
            g_hist[i] = 0;
            g_bump[i] = 0;
        }
    }

    if (tid < SC_ITEMS) {
        int idx = start + tid;
        if (idx < B) {
            int4 pk = __ldg(&g_pack[idx]);  // coalesced {b, h, r, t}
            sh_b[tid] = pk.x; sh_h[tid] = pk.y;
            sh_r[tid] = pk.z; sh_t[tid] = pk.w;
        } else {
            sh_b[tid] = -1; sh_h[tid] = 0; sh_r[tid] = 0; sh_t[tid] = 0;
        }
    }
    __syncthreads();

    const float4* ve4 = reinterpret_cast<const float4*>(g_ve);
    #pragma unroll
    for (int p = 0; p < 2; p++) {
        int i = p * SC_THREADS + tid;       // 0..511
        int item = i >> 3;
        int chunk = i & 7;
        int sw = item * 8 + ((chunk + item) & 7);
        sv_h[sw] = __ldg(ve4 + (size_t)sh_h[item] * 8 + chunk);
        sv_t[sw] = __ldg(ve4 + (size_t)sh_t[item] * 8 + chunk);
    }
    __syncthreads();

    const int s = tid >> 6;        // row-slice 0..3 (warp-uniform)
    const int item = tid & 63;

    float2 vh[16];
    #pragma unroll
    for (int j = 0; j < 8; j++) {
        float4 a = sv_h[item * 8 + ((j + item) & 7)];
        vh[2 * j]     = make_float2(a.x, a.y);
        vh[2 * j + 1] = make_float2(a.z, a.w);
    }

    const float4* M4 = reinterpret_cast<const float4*>(g_mr) + (size_t)sh_r[item] * 128 + s * 32;
    const float2* vt2 = reinterpret_cast<const float2*>(sv_t);
    float acc = 0.0f;
    #pragma unroll
    for (int ir = 0; ir < 4; ir++) {
        float2 u = make_float2(0.0f, 0.0f);
        #pragma unroll
        for (int j4 = 0; j4 < 8; j4++) {
            float4 mm = __ldg(M4 + ir * 8 + j4);
            float2 a0 = vh[2 * j4];
            float2 a1 = vh[2 * j4 + 1];
            u.x += mm.x * a0.x - mm.y * a0.y + mm.z * a1.x - mm.w * a1.y;
            u.y += mm.x * a0.y + mm.y * a0.x + mm.z * a1.y + mm.w * a1.x;
        }
        // vt element 4s+ir lives in chunk 2s+(ir>>1), component ir&1 (swizzled).
        int sw = item * 8 + ((2 * s + (ir >> 1) + item) & 7);
        float2 vtv = vt2[sw * 2 + (ir & 1)];
        acc += vtv.x * u.x + vtv.y * u.y;  // Re(conj(vt)*u)
    }
    sred[s * SC_ITEMS + item] = acc;
    __syncthreads();

    if (tid < SC_ITEMS) {
        int b = sh_b[tid];
        if (b >= 0) {
            out[b] = sred[tid] + sred[SC_ITEMS + tid] +
                     sred[2 * SC_ITEMS + tid] + sred[3 * SC_ITEMS + tid];
        }
    }
}

// ---------------------------------------------------------------------------
// Launch: prep -> scatter -> score (3 kernels).
// ---------------------------------------------------------------------------
extern "C" void kernel_launch(void* const* d_in, const int* in_sizes, int n_in,
                              void* d_out, int out_size) {
    const float* ep = (const float*)d_in[0];  // entity_params   [E,4,4,3]
    const float* rp = (const float*)d_in[1];  // relation_params [R,4,4,3]
    const int* h = (const int*)d_in[2];
    const int* r = (const int*)d_in[3];
    const int* t = (const int*)d_in[4];
    float* out = (float*)d_out;

    int E = in_sizes[0] / 48;
    int R = in_sizes[1] / 48;
    int B = in_sizes[2];

    int EB = (E + 255) / 256;           // 1 thread per entity
    int RB = (R * 16 + 255) / 256;

    prep_kernel<<<EB + RB + HIST_BLOCKS, 256>>>(ep, E, EB, rp, R, RB, r, B);
    scatter_kernel<<<SCAT_BLOCKS, 256>>>(h, r, t, B);
    score_kernel<<<(B + SC_ITEMS - 1) / SC_ITEMS, SC_THREADS>>>(out, B);
}

// round 16
// speedup vs baseline: 1.4294x; 1.4294x over previous
#include <cuda_runtime.h>

// Problem constants (shapes fixed by the dataset).
#define NE_MAX 100000
#define NR_MAX 1000
#define NB_MAX 131072

// Scratch (allocation-free: __device__ globals, zero-initialized at load).
__device__ float2 g_ve[NE_MAX * 16];   // 12.8 MB per-entity state vectors
__device__ float2 g_mr[NR_MAX * 256];  // 2.0 MB per-relation 16x16 matrices
__device__ int g_hist[NR_MAX];         // relation counts   (INVARIANT: zero at entry)
__device__ int g_bump[NR_MAX];         // per-bin bump ctrs (INVARIANT: zero at entry)
__device__ int4 g_pack[NB_MAX];        // relation-grouped {b, h[b], r[b], t[b]}

// ---------------------------------------------------------------------------
// Gate math. Angles in [-pi/10, pi/10] -> __sincosf is inside the 1e-3 budget.
// ---------------------------------------------------------------------------
__device__ __forceinline__ void rot_mat(float phi, float th, float om,
                                        float2& m00, float2& m01,
                                        float2& m10, float2& m11) {
    float st, ct, sa, ca, sb, cb;
    __sincosf(0.5f * th, &st, &ct);
    __sincosf(0.5f * (phi + om), &sa, &ca);
    __sincosf(0.5f * (phi - om), &sb, &cb);
    m00 = make_float2(ca * ct, -sa * ct);
    m01 = make_float2(-cb * st, -sb * st);
    m10 = make_float2(cb * st, -sb * st);
    m11 = make_float2(ca * ct, sa * ct);
}

__device__ __forceinline__ float2 cmul(float2 x, float2 y) {
    return make_float2(x.x * y.x - x.y * y.y, x.x * y.y + x.y * y.x);
}

__device__ __forceinline__ float2 cadd(float2 x, float2 y) {
    return make_float2(x.x + y.x, x.y + y.y);
}

__device__ __forceinline__ void gate_pair(float2& a, float2& b,
                                          float2 m00, float2 m01,
                                          float2 m10, float2 m11) {
    float2 na, nb;
    na.x = m00.x * a.x - m00.y * a.y + m01.x * b.x - m01.y * b.y;
    na.y = m00.x * a.y + m00.y * a.x + m01.x * b.y + m01.y * b.x;
    nb.x = m10.x * a.x - m10.y * a.y + m11.x * b.x - m11.y * b.y;
    nb.y = m10.x * a.y + m10.y * a.x + m11.x * b.y + m11.y * b.x;
    a = na; b = nb;
}

// CRot layers (off = 1..3) on a full 16-amplitude register state.
__device__ __forceinline__ void apply_crot_layers(float2 s[16], const float p[48]) {
    #pragma unroll
    for (int off = 1; off <= 3; off++) {
        #pragma unroll
        for (int q = 0; q < 4; q++) {
            const int t = (q + off) & 3;
            const int base = (off * 4 + q) * 3;
            float2 m00, m01, m10, m11;
            rot_mat(p[base + 0], p[base + 1], p[base + 2], m00, m01, m10, m11);
            const int sc = 8 >> q;
            const int st = 8 >> t;
            #pragma unroll
            for (int i = 0; i < 16; i++) {
                if (!(i & sc) || (i & st)) continue;  // control=1, target bit=0
                gate_pair(s[i], s[i + st], m00, m01, m10, m11);
            }
        }
    }
}

__device__ __forceinline__ void load_params48(const float* __restrict__ g, float p[48]) {
    const float4* g4 = reinterpret_cast<const float4*>(g);
    #pragma unroll
    for (int i = 0; i < 12; i++) {
        float4 v = __ldg(g4 + i);
        p[i * 4 + 0] = v.x; p[i * 4 + 1] = v.y;
        p[i * 4 + 2] = v.z; p[i * 4 + 3] = v.w;
    }
}

// Build s[16] = product state from per-qubit 2-vectors w0..w3.
__device__ __forceinline__ void build_product(float2 s[16],
                                              const float2 w0[2], const float2 w1[2],
                                              const float2 w2[2], const float2 w3[2]) {
    float2 a01[4], a23[4];
    #pragma unroll
    for (int k = 0; k < 4; k++) {
        a01[k] = cmul(w0[k >> 1], w1[k & 1]);
        a23[k] = cmul(w2[k >> 1], w3[k & 1]);
    }
    #pragma unroll
    for (int i = 0; i < 16; i++)
        s[i] = cmul(a01[i >> 2], a23[i & 3]);
}

// ---------------------------------------------------------------------------
// Fused prep kernel: entities | relations | histogram, split by blockIdx.
// Layer 0 uses the product-state shortcut in both circuit jobs.
// ---------------------------------------------------------------------------
#define HIST_BLOCKS 64

__global__ void prep_kernel(const float* __restrict__ ep, int E, int EB,
                            const float* __restrict__ rp, int R, int RB,
                            const int* __restrict__ r, int B) {
    __shared__ int sh[NR_MAX];

    if (blockIdx.x < EB) {
        // ---- entity job: v_e = U(ep[e]) * |+>^4 ----
        int e = blockIdx.x * blockDim.x + threadIdx.x;
        if (e >= E) return;
        float p[48];
        load_params48(ep + (size_t)e * 48, p);

        float2 w[4][2];
        #pragma unroll
        for (int q = 0; q < 4; q++) {
            float2 m00, m01, m10, m11;
            rot_mat(p[q * 3 + 0], p[q * 3 + 1], p[q * 3 + 2], m00, m01, m10, m11);
            w[q][0] = cadd(m00, m01);
            w[q][1] = cadd(m10, m11);
        }
        w[0][0].x *= 0.25f; w[0][0].y *= 0.25f;
        w[0][1].x *= 0.25f; w[0][1].y *= 0.25f;

        float2 s[16];
        build_product(s, w[0], w[1], w[2], w[3]);
        apply_crot_layers(s, p);

        float4* dst = reinterpret_cast<float4*>(g_ve + e * 16);
        #pragma unroll
        for (int i = 0; i < 8; i++)
            dst[i] = make_float4(s[2 * i].x, s[2 * i].y, s[2 * i + 1].x, s[2 * i + 1].y);
    } else if (blockIdx.x < EB + RB) {
        // ---- relation job: M_r column col = U(rp[r]) * e_col ----
        int idx = (blockIdx.x - EB) * blockDim.x + threadIdx.x;
        int rr = idx >> 4;
        int col = idx & 15;
        if (rr >= R) return;
        float p[48];
        load_params48(rp + (size_t)rr * 48, p);

        float2 w[4][2];
        #pragma unroll
        for (int q = 0; q < 4; q++) {
            float2 m00, m01, m10, m11;
            rot_mat(p[q * 3 + 0], p[q * 3 + 1], p[q * 3 + 2], m00, m01, m10, m11);
            int cb = (col >> (3 - q)) & 1;     // qubit q's bit of |col>
            w[q][0] = cb ? m01 : m00;
            w[q][1] = cb ? m11 : m10;
        }

        float2 s[16];
        build_product(s, w[0], w[1], w[2], w[3]);
        apply_crot_layers(s, p);

        #pragma unroll
        for (int i = 0; i < 16; i++)
            g_mr[rr * 256 + i * 16 + col] = s[i];
    } else {
        // ---- histogram job (smem-privatized; g_hist zero at entry) ----
        int hb = blockIdx.x - EB - RB;
        for (int i = threadIdx.x; i < NR_MAX; i += blockDim.x) sh[i] = 0;
        __syncthreads();
        int chunk = (B + HIST_BLOCKS - 1) / HIST_BLOCKS;
        int start = hb * chunk;
        int end = min(start + chunk, B);
        for (int b = start + threadIdx.x; b < end; b += blockDim.x)
            atomicAdd(&sh[r[b]], 1);
        __syncthreads();
        for (int i = threadIdx.x; i < NR_MAX; i += blockDim.x) {
            int c = sh[i];
            if (c) atomicAdd(&g_hist[i], c);
        }
    }
}

// ---------------------------------------------------------------------------
// Scatter with integrated scan (proven 64-block round-9/14 version).
// ---------------------------------------------------------------------------
#define SCAT_BLOCKS 64

__global__ void __launch_bounds__(256) scatter_kernel(
        const int* __restrict__ h, const int* __restrict__ r,
        const int* __restrict__ t, int B) {
    __shared__ int cnt[NR_MAX];
    __shared__ int gbase[NR_MAX];
    __shared__ int wbase[NR_MAX];
    __shared__ int wsum[8];

    const int tid = threadIdx.x;
    for (int i = tid; i < NR_MAX; i += blockDim.x) cnt[i] = 0;

    int hv[4], pre[4];
    int tsum = 0;
    #pragma unroll
    for (int k = 0; k < 4; k++) {
        int bin = 4 * tid + k;
        hv[k] = (bin < NR_MAX) ? g_hist[bin] : 0;
        pre[k] = tsum;
        tsum += hv[k];
    }
    int x = tsum;
    #pragma unroll
    for (int d = 1; d < 32; d <<= 1) {
        int y = __shfl_up_sync(0xffffffffu, x, d);
        if ((tid & 31) >= d) x += y;
    }
    if ((tid & 31) == 31) wsum[tid >> 5] = x;
    __syncthreads();
    if (tid < 8) {
        int s = wsum[tid];
        #pragma unroll
        for (int d = 1; d < 8; d <<= 1) {
            int y = __shfl_up_sync(0xffu, s, d);
            if (tid >= d) s += y;
        }
        wsum[tid] = s;
    }
    __syncthreads();
    int excl = x - tsum + ((tid >= 32) ? wsum[(tid >> 5) - 1] : 0);
    #pragma unroll
    for (int k = 0; k < 4; k++) {
        int bin = 4 * tid + k;
        if (bin < NR_MAX) gbase[bin] = excl + pre[k];
    }
    __syncthreads();

    int chunk = (B + SCAT_BLOCKS - 1) / SCAT_BLOCKS;
    int start = blockIdx.x * chunk;
    int end = min(start + chunk, B);
    for (int b = start + tid; b < end; b += blockDim.x)
        atomicAdd(&cnt[r[b]], 1);
    __syncthreads();

    for (int i = tid; i < NR_MAX; i += blockDim.x) {
        int c = cnt[i];
        wbase[i] = c ? gbase[i] + atomicAdd(&g_bump[i], c) : 0;
        cnt[i] = 0;
    }
    __syncthreads();

    for (int b = start + tid; b < end; b += blockDim.x) {
        int rr = r[b];
        int pos = wbase[rr] + atomicAdd(&cnt[rr], 1);
        g_pack[pos] = make_int4(b, h[b], rr, t[b]);
    }
}

// ---------------------------------------------------------------------------
// Score: 4 threads per item, 4 rows each. vt read from smem at accumulate
// time (-8 live regs). NO minBlocks clause — let ptxas allocate naturally;
// if regs land <=42 we get 6 blocks/SM for free, with zero spill risk.
// ---------------------------------------------------------------------------
#define SC_ITEMS 64            // items per block
#define SC_THREADS 256         // 4 threads per item

__global__ void __launch_bounds__(SC_THREADS) score_kernel(float* __restrict__ out, int B) {
    __shared__ float4 sv_h[SC_ITEMS * 8];   // 4 KB, (chunk+item)&7 swizzle
    __shared__ float4 sv_t[SC_ITEMS * 8];   // 4 KB
    __shared__ int sh_h[SC_ITEMS];
    __shared__ int sh_t[SC_ITEMS];
    __shared__ int sh_r[SC_ITEMS];
    __shared__ int sh_b[SC_ITEMS];
    __shared__ float sred[SC_THREADS];

    const int tid = threadIdx.x;
    const int start = blockIdx.x * SC_ITEMS;

    // Re-zero sort scratch for the next graph replay (block 0 only).
    if (blockIdx.x == 0) {
        for (int i = tid; i < NR_MAX; i += SC_THREADS) {
            g_hist[i] = 0;
            g_bump[i] = 0;
        }
    }

    if (tid < SC_ITEMS) {
        int idx = start + tid;
        if (idx < B) {
            int4 pk = __ldg(&g_pack[idx]);  // coalesced {b, h, r, t}
            sh_b[tid] = pk.x; sh_h[tid] = pk.y;
            sh_r[tid] = pk.z; sh_t[tid] = pk.w;
        } else {
            sh_b[tid] = -1; sh_h[tid] = 0; sh_r[tid] = 0; sh_t[tid] = 0;
        }
    }
    __syncthreads();

    const float4* ve4 = reinterpret_cast<const float4*>(g_ve);
    #pragma unroll
    for (int p = 0; p < 2; p++) {
        int i = p * SC_THREADS + tid;       // 0..511
        int item = i >> 3;
        int chunk = i & 7;
        int sw = item * 8 + ((chunk + item) & 7);
        sv_h[sw] = __ldg(ve4 + (size_t)sh_h[item] * 8 + chunk);
        sv_t[sw] = __ldg(ve4 + (size_t)sh_t[item] * 8 + chunk);
    }
    __syncthreads();

    const int s = tid >> 6;        // row-slice 0..3 (warp-uniform)
    const int item = tid & 63;

    float2 vh[16];
    #pragma unroll
    for (int j = 0; j < 8; j++) {
        float4 a = sv_h[item * 8 + ((j + item) & 7)];
        vh[2 * j]     = make_float2(a.x, a.y);
        vh[2 * j + 1] = make_float2(a.z, a.w);
    }

    const float4* M4 = reinterpret_cast<const float4*>(g_mr) + (size_t)sh_r[item] * 128 + s * 32;
    const float2* vt2 = reinterpret_cast<const float2*>(sv_t);
    float acc = 0.0f;
    #pragma unroll
    for (int ir = 0; ir < 4; ir++) {
        float2 u = make_float2(0.0f, 0.0f);
        #pragma unroll
        for (int j4 = 0; j4 < 8; j4++) {
            float4 mm = __ldg(M4 + ir * 8 + j4);
            float2 a0 = vh[2 * j4];
            float2 a1 = vh[2 * j4 + 1];
            u.x += mm.x * a0.x - mm.y * a0.y + mm.z * a1.x - mm.w * a1.y;
            u.y += mm.x * a0.y + mm.y * a0.x + mm.z * a1.y + mm.w * a1.x;
        }
        // vt element 4s+ir lives in chunk 2s+(ir>>1), component ir&1 (swizzled).
        int sw = item * 8 + ((2 * s + (ir >> 1) + item) & 7);
        float2 vtv = vt2[sw * 2 + (ir & 1)];
        acc += vtv.x * u.x + vtv.y * u.y;  // Re(conj(vt)*u)
    }
    sred[s * SC_ITEMS + item] = acc;
    __syncthreads();

    if (tid < SC_ITEMS) {
        int b = sh_b[tid];
        if (b >= 0) {
            out[b] = sred[tid] + sred[SC_ITEMS + tid] +
                     sred[2 * SC_ITEMS + tid] + sred[3 * SC_ITEMS + tid];
        }
    }
}

// ---------------------------------------------------------------------------
// Launch: prep -> scatter -> score (3 kernels).
// ---------------------------------------------------------------------------
extern "C" void kernel_launch(void* const* d_in, const int* in_sizes, int n_in,
                              void* d_out, int out_size) {
    const float* ep = (const float*)d_in[0];  // entity_params   [E,4,4,3]
    const float* rp = (const float*)d_in[1];  // relation_params [R,4,4,3]
    const int* h = (const int*)d_in[2];
    const int* r = (const int*)d_in[3];
    const int* t = (const int*)d_in[4];
    float* out = (float*)d_out;

    int E = in_sizes[0] / 48;
    int R = in_sizes[1] / 48;
    int B = in_sizes[2];

    int EB = (E + 255) / 256;           // 1 thread per entity
    int RB = (R * 16 + 255) / 256;

    prep_kernel<<<EB + RB + HIST_BLOCKS, 256>>>(ep, E, EB, rp, R, RB, r, B);
    scatter_kernel<<<SCAT_BLOCKS, 256>>>(h, r, t, B);
    score_kernel<<<(B + SC_ITEMS - 1) / SC_ITEMS, SC_THREADS>>>(out, B);
}

// round 17
// speedup vs baseline: 1.5441x; 1.0802x over previous
#include <cuda_runtime.h>

// Problem constants (shapes fixed by the dataset).
#define NE_MAX 100000
#define NR_MAX 1000
#define NB_MAX 131072

// Scratch (allocation-free: __device__ globals, zero-initialized at load).
__device__ float2 g_ve[NE_MAX * 16];   // 12.8 MB per-entity state vectors
__device__ float2 g_mr[NR_MAX * 256];  // 2.0 MB per-relation 16x16 matrices
__device__ int g_hist[NR_MAX];         // relation counts   (INVARIANT: zero at entry)
__device__ int g_bump[NR_MAX];         // per-bin bump ctrs (INVARIANT: zero at entry)
__device__ int4 g_pack[NB_MAX];        // relation-grouped {b, h[b], r[b], t[b]}

// ---------------------------------------------------------------------------
// Gate math. Angles in [-pi/10, pi/10] -> __sincosf is inside the 1e-3 budget.
// ---------------------------------------------------------------------------
__device__ __forceinline__ void rot_mat(float phi, float th, float om,
                                        float2& m00, float2& m01,
                                        float2& m10, float2& m11) {
    float st, ct, sa, ca, sb, cb;
    __sincosf(0.5f * th, &st, &ct);
    __sincosf(0.5f * (phi + om), &sa, &ca);
    __sincosf(0.5f * (phi - om), &sb, &cb);
    m00 = make_float2(ca * ct, -sa * ct);
    m01 = make_float2(-cb * st, -sb * st);
    m10 = make_float2(cb * st, -sb * st);
    m11 = make_float2(ca * ct, sa * ct);
}

__device__ __forceinline__ float2 cmul(float2 x, float2 y) {
    return make_float2(x.x * y.x - x.y * y.y, x.x * y.y + x.y * y.x);
}

__device__ __forceinline__ float2 cadd(float2 x, float2 y) {
    return make_float2(x.x + y.x, x.y + y.y);
}

__device__ __forceinline__ void gate_pair(float2& a, float2& b,
                                          float2 m00, float2 m01,
                                          float2 m10, float2 m11) {
    float2 na, nb;
    na.x = m00.x * a.x - m00.y * a.y + m01.x * b.x - m01.y * b.y;
    na.y = m00.x * a.y + m00.y * a.x + m01.x * b.y + m01.y * b.x;
    nb.x = m10.x * a.x - m10.y * a.y + m11.x * b.x - m11.y * b.y;
    nb.y = m10.x * a.y + m10.y * a.x + m11.x * b.y + m11.y * b.x;
    a = na; b = nb;
}

// CRot layers (off = 1..3) on a full 16-amplitude register state.
__device__ __forceinline__ void apply_crot_layers(float2 s[16], const float p[48]) {
    #pragma unroll
    for (int off = 1; off <= 3; off++) {
        #pragma unroll
        for (int q = 0; q < 4; q++) {
            const int t = (q + off) & 3;
            const int base = (off * 4 + q) * 3;
            float2 m00, m01, m10, m11;
            rot_mat(p[base + 0], p[base + 1], p[base + 2], m00, m01, m10, m11);
            const int sc = 8 >> q;
            const int st = 8 >> t;
            #pragma unroll
            for (int i = 0; i < 16; i++) {
                if (!(i & sc) || (i & st)) continue;  // control=1, target bit=0
                gate_pair(s[i], s[i + st], m00, m01, m10, m11);
            }
        }
    }
}

__device__ __forceinline__ void load_params48(const float* __restrict__ g, float p[48]) {
    const float4* g4 = reinterpret_cast<const float4*>(g);
    #pragma unroll
    for (int i = 0; i < 12; i++) {
        float4 v = __ldg(g4 + i);
        p[i * 4 + 0] = v.x; p[i * 4 + 1] = v.y;
        p[i * 4 + 2] = v.z; p[i * 4 + 3] = v.w;
    }
}

// Build s[16] = product state from per-qubit 2-vectors w0..w3.
__device__ __forceinline__ void build_product(float2 s[16],
                                              const float2 w0[2], const float2 w1[2],
                                              const float2 w2[2], const float2 w3[2]) {
    float2 a01[4], a23[4];
    #pragma unroll
    for (int k = 0; k < 4; k++) {
        a01[k] = cmul(w0[k >> 1], w1[k & 1]);
        a23[k] = cmul(w2[k >> 1], w3[k & 1]);
    }
    #pragma unroll
    for (int i = 0; i < 16; i++)
        s[i] = cmul(a01[i >> 2], a23[i & 3]);
}

// ---------------------------------------------------------------------------
// Fused prep kernel: entities | relations | histogram, split by blockIdx.
// Layer 0 uses the product-state shortcut in both circuit jobs.
// ---------------------------------------------------------------------------
#define HIST_BLOCKS 64

__global__ void prep_kernel(const float* __restrict__ ep, int E, int EB,
                            const float* __restrict__ rp, int R, int RB,
                            const int* __restrict__ r, int B) {
    __shared__ int sh[NR_MAX];

    if (blockIdx.x < EB) {
        // ---- entity job: v_e = U(ep[e]) * |+>^4 ----
        int e = blockIdx.x * blockDim.x + threadIdx.x;
        if (e >= E) return;
        float p[48];
        load_params48(ep + (size_t)e * 48, p);

        float2 w[4][2];
        #pragma unroll
        for (int q = 0; q < 4; q++) {
            float2 m00, m01, m10, m11;
            rot_mat(p[q * 3 + 0], p[q * 3 + 1], p[q * 3 + 2], m00, m01, m10, m11);
            w[q][0] = cadd(m00, m01);
            w[q][1] = cadd(m10, m11);
        }
        w[0][0].x *= 0.25f; w[0][0].y *= 0.25f;
        w[0][1].x *= 0.25f; w[0][1].y *= 0.25f;

        float2 s[16];
        build_product(s, w[0], w[1], w[2], w[3]);
        apply_crot_layers(s, p);

        float4* dst = reinterpret_cast<float4*>(g_ve + e * 16);
        #pragma unroll
        for (int i = 0; i < 8; i++)
            dst[i] = make_float4(s[2 * i].x, s[2 * i].y, s[2 * i + 1].x, s[2 * i + 1].y);
    } else if (blockIdx.x < EB + RB) {
        // ---- relation job: M_r column col = U(rp[r]) * e_col ----
        int idx = (blockIdx.x - EB) * blockDim.x + threadIdx.x;
        int rr = idx >> 4;
        int col = idx & 15;
        if (rr >= R) return;
        float p[48];
        load_params48(rp + (size_t)rr * 48, p);

        float2 w[4][2];
        #pragma unroll
        for (int q = 0; q < 4; q++) {
            float2 m00, m01, m10, m11;
            rot_mat(p[q * 3 + 0], p[q * 3 + 1], p[q * 3 + 2], m00, m01, m10, m11);
            int cb = (col >> (3 - q)) & 1;     // qubit q's bit of |col>
            w[q][0] = cb ? m01 : m00;
            w[q][1] = cb ? m11 : m10;
        }

        float2 s[16];
        build_product(s, w[0], w[1], w[2], w[3]);
        apply_crot_layers(s, p);

        #pragma unroll
        for (int i = 0; i < 16; i++)
            g_mr[rr * 256 + i * 16 + col] = s[i];
    } else {
        // ---- histogram job (smem-privatized; g_hist zero at entry) ----
        int hb = blockIdx.x - EB - RB;
        for (int i = threadIdx.x; i < NR_MAX; i += blockDim.x) sh[i] = 0;
        __syncthreads();
        int chunk = (B + HIST_BLOCKS - 1) / HIST_BLOCKS;
        int start = hb * chunk;
        int end = min(start + chunk, B);
        for (int b = start + threadIdx.x; b < end; b += blockDim.x)
            atomicAdd(&sh[r[b]], 1);
        __syncthreads();
        for (int i = threadIdx.x; i < NR_MAX; i += blockDim.x) {
            int c = sh[i];
            if (c) atomicAdd(&g_hist[i], c);
        }
    }
}

// ---------------------------------------------------------------------------
// Scatter with integrated scan (proven 64-block round-9/14 version).
// ---------------------------------------------------------------------------
#define SCAT_BLOCKS 64

__global__ void __launch_bounds__(256) scatter_kernel(
        const int* __restrict__ h, const int* __restrict__ r,
        const int* __restrict__ t, int B) {
    __shared__ int cnt[NR_MAX];
    __shared__ int gbase[NR_MAX];
    __shared__ int wbase[NR_MAX];
    __shared__ int wsum[8];

    const int tid = threadIdx.x;
    for (int i = tid; i < NR_MAX; i += blockDim.x) cnt[i] = 0;

    int hv[4], pre[4];
    int tsum = 0;
    #pragma unroll
    for (int k = 0; k < 4; k++) {
        int bin = 4 * tid + k;
        hv[k] = (bin < NR_MAX) ? g_hist[bin] : 0;
        pre[k] = tsum;
        tsum += hv[k];
    }
    int x = tsum;
    #pragma unroll
    for (int d = 1; d < 32; d <<= 1) {
        int y = __shfl_up_sync(0xffffffffu, x, d);
        if ((tid & 31) >= d) x += y;
    }
    if ((tid & 31) == 31) wsum[tid >> 5] = x;
    __syncthreads();
    if (tid < 8) {
        int s = wsum[tid];
        #pragma unroll
        for (int d = 1; d < 8; d <<= 1) {
            int y = __shfl_up_sync(0xffu, s, d);
            if (tid >= d) s += y;
        }
        wsum[tid] = s;
    }
    __syncthreads();
    int excl = x - tsum + ((tid >= 32) ? wsum[(tid >> 5) - 1] : 0);
    #pragma unroll
    for (int k = 0; k < 4; k++) {
        int bin = 4 * tid + k;
        if (bin < NR_MAX) gbase[bin] = excl + pre[k];
    }
    __syncthreads();

    int chunk = (B + SCAT_BLOCKS - 1) / SCAT_BLOCKS;
    int start = blockIdx.x * chunk;
    int end = min(start + chunk, B);
    for (int b = start + tid; b < end; b += blockDim.x)
        atomicAdd(&cnt[r[b]], 1);
    __syncthreads();

    for (int i = tid; i < NR_MAX; i += blockDim.x) {
        int c = cnt[i];
        wbase[i] = c ? gbase[i] + atomicAdd(&g_bump[i], c) : 0;
        cnt[i] = 0;
    }
    __syncthreads();

    for (int b = start + tid; b < end; b += blockDim.x) {
        int rr = r[b];
        int pos = wbase[rr] + atomicAdd(&cnt[rr], 1);
        g_pack[pos] = make_int4(b, h[b], rr, t[b]);
    }
}

// ---------------------------------------------------------------------------
// Score (round-14 proven math, smaller blocks): 4 threads per item, vt in
// registers. 128-thread blocks: 46 regs x 128 = 5888 -> 11 blocks/SM =
// 68.75% occupancy ceiling (vs 62.5% at 256 threads), finer wave balance.
// Slice s = warp index (warp-uniform -> M loads stay broadcasts).
// ---------------------------------------------------------------------------
#define SC_ITEMS 32            // items per block
#define SC_THREADS 128         // 4 threads per item (4 warps = 4 row-slices)

__global__ void __launch_bounds__(SC_THREADS) score_kernel(float* __restrict__ out, int B) {
    __shared__ float4 sv_h[SC_ITEMS * 8];   // 2 KB, (chunk+item)&7 swizzle
    __shared__ float4 sv_t[SC_ITEMS * 8];   // 2 KB
    __shared__ int sh_h[SC_ITEMS];
    __shared__ int sh_t[SC_ITEMS];
    __shared__ int sh_r[SC_ITEMS];
    __shared__ int sh_b[SC_ITEMS];
    __shared__ float sred[SC_THREADS];

    const int tid = threadIdx.x;
    const int start = blockIdx.x * SC_ITEMS;

    // Re-zero sort scratch for the next graph replay (block 0 only).
    if (blockIdx.x == 0) {
        for (int i = tid; i < NR_MAX; i += SC_THREADS) {
            g_hist[i] = 0;
            g_bump[i] = 0;
        }
    }

    if (tid < SC_ITEMS) {
        int idx = start + tid;
        if (idx < B) {
            int4 pk = __ldg(&g_pack[idx]);  // coalesced {b, h, r, t}
            sh_b[tid] = pk.x; sh_h[tid] = pk.y;
            sh_r[tid] = pk.z; sh_t[tid] = pk.w;
        } else {
            sh_b[tid] = -1; sh_h[tid] = 0; sh_r[tid] = 0; sh_t[tid] = 0;
        }
    }
    __syncthreads();

    // Cooperative staging: 32 items x 8 chunks = 256 float4 per vector,
    // 2 rounds of 128 threads. 8 lanes cover one 128B line.
    const float4* ve4 = reinterpret_cast<const float4*>(g_ve);
    #pragma unroll
    for (int p = 0; p < 2; p++) {
        int i = p * SC_THREADS + tid;       // 0..255
        int item = i >> 3;
        int chunk = i & 7;
        int sw = item * 8 + ((chunk + item) & 7);
        sv_h[sw] = __ldg(ve4 + (size_t)sh_h[item] * 8 + chunk);
        sv_t[sw] = __ldg(ve4 + (size_t)sh_t[item] * 8 + chunk);
    }
    __syncthreads();

    const int s = tid >> 5;        // row-slice 0..3 (= warp index, uniform)
    const int item = tid & 31;     // item within block (= lane)

    // Full vh into registers (swizzled conflict-free LDS.128).
    float2 vh[16];
    #pragma unroll
    for (int j = 0; j < 8; j++) {
        float4 a = sv_h[item * 8 + ((j + item) & 7)];
        vh[2 * j]     = make_float2(a.x, a.y);
        vh[2 * j + 1] = make_float2(a.z, a.w);
    }
    // This slice's 4 vt entries (chunks 2s, 2s+1).
    float2 vt[4];
    #pragma unroll
    for (int c = 0; c < 2; c++) {
        float4 v = sv_t[item * 8 + ((2 * s + c + item) & 7)];
        vt[2 * c]     = make_float2(v.x, v.y);
        vt[2 * c + 1] = make_float2(v.z, v.w);
    }

    // 4 rows of u = M * vh; accumulate Re(conj(vt_i) * u_i).
    const float4* M4 = reinterpret_cast<const float4*>(g_mr) + (size_t)sh_r[item] * 128 + s * 32;
    float acc = 0.0f;
    #pragma unroll
    for (int ir = 0; ir < 4; ir++) {
        float2 u = make_float2(0.0f, 0.0f);
        #pragma unroll
        for (int j4 = 0; j4 < 8; j4++) {
            float4 mm = __ldg(M4 + ir * 8 + j4);
            float2 a0 = vh[2 * j4];
            float2 a1 = vh[2 * j4 + 1];
            u.x += mm.x * a0.x - mm.y * a0.y + mm.z * a1.x - mm.w * a1.y;
            u.y += mm.x * a0.y + mm.y * a0.x + mm.z * a1.y + mm.w * a1.x;
        }
        acc += vt[ir].x * u.x + vt[ir].y * u.y;
    }
    sred[s * SC_ITEMS + item] = acc;
    __syncthreads();

    if (tid < SC_ITEMS) {
        int b = sh_b[tid];
        if (b >= 0) {
            out[b] = sred[tid] + sred[SC_ITEMS + tid] +
                     sred[2 * SC_ITEMS + tid] + sred[3 * SC_ITEMS + tid];
        }
    }
}

// ---------------------------------------------------------------------------
// Launch: prep -> scatter -> score (3 kernels).
// ---------------------------------------------------------------------------
extern "C" void kernel_launch(void* const* d_in, const int* in_sizes, int n_in,
                              void* d_out, int out_size) {
    const float* ep = (const float*)d_in[0];  // entity_params   [E,4,4,3]
    const float* rp = (const float*)d_in[1];  // relation_params [R,4,4,3]
    const int* h = (const int*)d_in[2];
    const int* r = (const int*)d_in[3];
    const int* t = (const int*)d_in[4];
    float* out = (float*)d_out;

    int E = in_sizes[0] / 48;
    int R = in_sizes[1] / 48;
    int B = in_sizes[2];

    int EB = (E + 255) / 256;           // 1 thread per entity
    int RB = (R * 16 + 255) / 256;

    prep_kernel<<<EB + RB + HIST_BLOCKS, 256>>>(ep, E, EB, rp, R, RB, r, B);
    scatter_kernel<<<SCAT_BLOCKS, 256>>>(h, r, t, B);
    score_kernel<<<(B + SC_ITEMS - 1) / SC_ITEMS, SC_THREADS>>>(out, B);
}